// round 1
// baseline (speedup 1.0000x reference)
#include <cuda_runtime.h>
#include <math.h>

#define Bn 64
#define Dn 256
#define Hn 512
#define Rn 32
#define CLIPV 50.0f
#define TI 8
#define TB 8

// Output layout (concatenation of the returned tuple, fp32):
//   v_new      [64,512]      @ 0
//   new_h      [64,512]      @ 32768
//   dU_new     [64,512,512]  @ 65536
//   new_trace_e[64,512]      @ 16842752
//   new_trace_E[64,512,512]  @ 16875520
#define OFF_V    ((size_t)0)
#define OFF_NH   ((size_t)32768)
#define OFF_DU   ((size_t)65536)
#define OFF_TEO  ((size_t)16842752)
#define OFF_TEE  ((size_t)16875520)

// Scratch (device globals: allocation-free)
__device__ float g_up[Hn * Hn];
__device__ float g_lo[Hn * Hn];
__device__ float g_mod[Bn];

__device__ __forceinline__ float sigmoidf_(float x) {
    return 1.0f / (1.0f + expf(-x));
}

// ---------------------------------------------------------------------------
// Kernel 0: precompute batch-independent clip bounds
//   upper[i,j] =  relu(CLIP - W_hh[i,j]) / (relu(alpha[i,j]) + 1e-8)
//   lower[i,j] = -relu(CLIP + W_hh[i,j]) / (relu(alpha[i,j]) + 1e-8)
// Hoisting this out of the main kernel removes 2 MUFU rcp per (b,i,j)
// element (33.6M -> 0.26M reciprocals).
// ---------------------------------------------------------------------------
__global__ void prep_uplo(const float* __restrict__ h2h_w,
                          const float* __restrict__ alpha) {
    const int i  = blockIdx.x;
    const int j0 = threadIdx.x * 4;
    const float4 W = *(const float4*)(h2h_w + (size_t)i * Hn + j0);
    const float4 A = *(const float4*)(alpha + (size_t)i * Hn + j0);
    float d0 = fmaxf(A.x, 0.f) + 1e-8f;
    float d1 = fmaxf(A.y, 0.f) + 1e-8f;
    float d2 = fmaxf(A.z, 0.f) + 1e-8f;
    float d3 = fmaxf(A.w, 0.f) + 1e-8f;
    float4 up, lo;
    up.x = fmaxf(CLIPV - W.x, 0.f) / d0;  lo.x = -fmaxf(CLIPV + W.x, 0.f) / d0;
    up.y = fmaxf(CLIPV - W.y, 0.f) / d1;  lo.y = -fmaxf(CLIPV + W.y, 0.f) / d1;
    up.z = fmaxf(CLIPV - W.z, 0.f) / d2;  lo.z = -fmaxf(CLIPV + W.z, 0.f) / d2;
    up.w = fmaxf(CLIPV - W.w, 0.f) / d3;  lo.w = -fmaxf(CLIPV + W.w, 0.f) / d3;
    *(float4*)(g_up + (size_t)i * Hn + j0) = up;
    *(float4*)(g_lo + (size_t)i * Hn + j0) = lo;
}

// ---------------------------------------------------------------------------
// Kernel 1: mod[b] = sum_{r<32} relu( x[b]·x2h_w[512+r] + x2h_b[512+r]
//                                   + h[b]·h2h_w[512+r] + h2h_b[512+r] )
// ---------------------------------------------------------------------------
__global__ void mod_kernel(const float* __restrict__ x,
                           const float* __restrict__ h,
                           const float* __restrict__ x2h_w,
                           const float* __restrict__ x2h_b,
                           const float* __restrict__ h2h_w,
                           const float* __restrict__ h2h_b) {
    const int b    = blockIdx.x;
    const int w    = threadIdx.x >> 5;
    const int lane = threadIdx.x & 31;
    __shared__ float sm[8];

    const float* xb = x + (size_t)b * Dn;
    const float* hb = h + (size_t)b * Hn;

    float acc = 0.f;
    for (int r = w; r < Rn; r += 8) {
        const int o = Hn + r;
        float s = 0.f;
        const float* xw = x2h_w + (size_t)o * Dn;
        for (int k = lane; k < Dn; k += 32) s = fmaf(xw[k], xb[k], s);
        const float* hw = h2h_w + (size_t)o * Hn;
        for (int k = lane; k < Hn; k += 32) s = fmaf(hw[k], hb[k], s);
#pragma unroll
        for (int off = 16; off; off >>= 1)
            s += __shfl_xor_sync(0xffffffffu, s, off);
        if (lane == 0) acc += fmaxf(s + x2h_b[o] + h2h_b[o], 0.f);
    }
    if (lane == 0) sm[w] = acc;
    __syncthreads();
    if (threadIdx.x == 0) {
        float m = 0.f;
#pragma unroll
        for (int ww = 0; ww < 8; ww++) m += sm[ww];
        g_mod[b] = m;
    }
}

// ---------------------------------------------------------------------------
// Kernel 2: fully fused main kernel.
// Block = tile of TI i-rows x TB batches. 128 threads; thread owns j0=tid*4.
// Per (i,b) row: single pass over dU / trace_E (each read exactly once),
// one block reduction for dv = Wx + Wh + plastic, then epilogue writes
// new_trace_E and clipped dU_new.
// ---------------------------------------------------------------------------
__global__ __launch_bounds__(128) void sgru_main(
    const float* __restrict__ x, const float* __restrict__ h,
    const float* __restrict__ v, const float* __restrict__ dU,
    const float* __restrict__ trace_e, const float* __restrict__ trace_E,
    const float* __restrict__ x2h_w, const float* __restrict__ x2h_b,
    const float* __restrict__ h2h_w, const float* __restrict__ h2h_b,
    const float* __restrict__ alpha, const float* __restrict__ tau_v,
    const float* __restrict__ tau_e, const float* __restrict__ tau_U,
    const float* __restrict__ tau_E, float* __restrict__ out) {
    const int i0  = blockIdx.x * TI;
    const int b0  = blockIdx.y * TB;
    const int tid = threadIdx.x;
    const int j0  = tid * 4;

    __shared__ float sh_h[TB][Hn];
    __shared__ float sh_te[TB][Hn];
    __shared__ float sh_x[TB][Dn];
    __shared__ float sred[2][4];

    // Stage per-batch vectors into shared (reused across all TI i-rows)
    for (int idx = tid; idx < TB * (Hn / 4); idx += 128) {
        const int bb = idx / (Hn / 4);
        const int jj = (idx % (Hn / 4)) * 4;
        *(float4*)&sh_h[bb][jj]  = *(const float4*)(h + (size_t)(b0 + bb) * Hn + jj);
        *(float4*)&sh_te[bb][jj] = *(const float4*)(trace_e + (size_t)(b0 + bb) * Hn + jj);
    }
    for (int idx = tid; idx < TB * (Dn / 4); idx += 128) {
        const int bb = idx / (Dn / 4);
        const int jj = (idx % (Dn / 4)) * 4;
        *(float4*)&sh_x[bb][jj] = *(const float4*)(x + (size_t)(b0 + bb) * Dn + jj);
    }
    __syncthreads();

    const float sU  = sigmoidf_(tau_U[0]);
    const float sE  = sigmoidf_(tau_E[0]);
    const float omU = 1.0f - sU;

    float modv[TB];
#pragma unroll
    for (int bb = 0; bb < TB; bb++) modv[bb] = g_mod[b0 + bb];

    int it = 0;
    for (int ii = 0; ii < TI; ii++) {
        const int i = i0 + ii;

        // per-i rows held in registers across the b-loop
        const float4 A  = *(const float4*)(alpha + (size_t)i * Hn + j0);
        const float ar0 = fmaxf(A.x, 0.f), ar1 = fmaxf(A.y, 0.f);
        const float ar2 = fmaxf(A.z, 0.f), ar3 = fmaxf(A.w, 0.f);
        const float4 W  = *(const float4*)(h2h_w + (size_t)i * Hn + j0);
        const float4 UP = *(const float4*)(g_up + (size_t)i * Hn + j0);
        const float4 LO = *(const float4*)(g_lo + (size_t)i * Hn + j0);
        float4 XW = make_float4(0.f, 0.f, 0.f, 0.f);
        if (j0 < Dn) XW = *(const float4*)(x2h_w + (size_t)i * Dn + j0);

        const float bias = x2h_b[i] + h2h_b[i];
        const float sv   = sigmoidf_(tau_v[i]);
        const float se   = sigmoidf_(tau_e[i]);

        for (int bb = 0; bb < TB; bb++) {
            const int b = b0 + bb;
            const size_t rowBase = ((size_t)b * Hn + i) * Hn;

            const float4 du = *(const float4*)(dU + rowBase + j0);
            const float4 tE = *(const float4*)(trace_E + rowBase + j0);
            const float h0 = sh_h[bb][j0],     h1 = sh_h[bb][j0 + 1];
            const float h2 = sh_h[bb][j0 + 2], h3 = sh_h[bb][j0 + 3];

            // partial of dv = Wx + Wh + plastic
            float p = ar0 * du.x * h0 + ar1 * du.y * h1 +
                      ar2 * du.z * h2 + ar3 * du.w * h3;
            p = fmaf(W.x, h0, p); p = fmaf(W.y, h1, p);
            p = fmaf(W.z, h2, p); p = fmaf(W.w, h3, p);
            if (j0 < Dn) {
                p = fmaf(XW.x, sh_x[bb][j0],     p);
                p = fmaf(XW.y, sh_x[bb][j0 + 1], p);
                p = fmaf(XW.z, sh_x[bb][j0 + 2], p);
                p = fmaf(XW.w, sh_x[bb][j0 + 3], p);
            }
#pragma unroll
            for (int off = 16; off; off >>= 1)
                p += __shfl_xor_sync(0xffffffffu, p, off);

            const int buf = it & 1;  // double buffer -> 1 sync per row
            if ((tid & 31) == 0) sred[buf][tid >> 5] = p;
            __syncthreads();
            const float dv = sred[buf][0] + sred[buf][1] +
                             sred[buf][2] + sred[buf][3] + bias;

            // per-row scalars (computed redundantly by all threads)
            const float vb  = v[(size_t)b * Hn + i];
            const float vn  = fmaf(sv, dv - vb, vb);
            const float nh  = fmaxf(vn, 0.f);
            const float nte = fmaf(se, sh_h[bb][i] - sh_te[bb][i], sh_te[bb][i]);
            if (tid == 0) {
                out[OFF_V   + (size_t)b * Hn + i] = vn;
                out[OFF_NH  + (size_t)b * Hn + i] = nh;
                out[OFF_TEO + (size_t)b * Hn + i] = nte;
            }

            const float suMod = sU * modv[bb];
            const float te0 = sh_te[bb][j0],     te1 = sh_te[bb][j0 + 1];
            const float te2 = sh_te[bb][j0 + 2], te3 = sh_te[bb][j0 + 3];

            const float o0 = nh * te0 - nte * h0;
            const float o1 = nh * te1 - nte * h1;
            const float o2 = nh * te2 - nte * h2;
            const float o3 = nh * te3 - nte * h3;

            const float t0 = fmaf(sE, o0 - tE.x, tE.x);
            const float t1 = fmaf(sE, o1 - tE.y, tE.y);
            const float t2 = fmaf(sE, o2 - tE.z, tE.z);
            const float t3 = fmaf(sE, o3 - tE.w, tE.w);

            float d0 = fmaf(suMod, t0, omU * du.x);
            float d1 = fmaf(suMod, t1, omU * du.y);
            float d2 = fmaf(suMod, t2, omU * du.z);
            float d3 = fmaf(suMod, t3, omU * du.w);
            d0 = fmaxf(fminf(d0, UP.x), LO.x);
            d1 = fmaxf(fminf(d1, UP.y), LO.y);
            d2 = fmaxf(fminf(d2, UP.z), LO.z);
            d3 = fmaxf(fminf(d3, UP.w), LO.w);

            *(float4*)(out + OFF_TEE + rowBase + j0) = make_float4(t0, t1, t2, t3);
            *(float4*)(out + OFF_DU  + rowBase + j0) = make_float4(d0, d1, d2, d3);
            it++;
        }
    }
}

extern "C" void kernel_launch(void* const* d_in, const int* in_sizes, int n_in,
                              void* d_out, int out_size) {
    const float* x       = (const float*)d_in[0];
    const float* h       = (const float*)d_in[1];
    const float* v       = (const float*)d_in[2];
    const float* dU      = (const float*)d_in[3];
    const float* trace_e = (const float*)d_in[4];
    const float* trace_E = (const float*)d_in[5];
    const float* x2h_w   = (const float*)d_in[6];
    const float* x2h_b   = (const float*)d_in[7];
    const float* h2h_w   = (const float*)d_in[8];
    const float* h2h_b   = (const float*)d_in[9];
    const float* alpha   = (const float*)d_in[10];
    const float* tau_v   = (const float*)d_in[11];
    const float* tau_e   = (const float*)d_in[12];
    const float* tau_U   = (const float*)d_in[13];
    const float* tau_E   = (const float*)d_in[14];
    float* out = (float*)d_out;

    prep_uplo<<<Hn, 128>>>(h2h_w, alpha);
    mod_kernel<<<Bn, 256>>>(x, h, x2h_w, x2h_b, h2h_w, h2h_b);
    dim3 grid(Hn / TI, Bn / TB);
    sgru_main<<<grid, 128>>>(x, h, v, dU, trace_e, trace_E, x2h_w, x2h_b,
                             h2h_w, h2h_b, alpha, tau_v, tau_e, tau_U, tau_E,
                             out);
}